// round 15
// baseline (speedup 1.0000x reference)
#include <cuda_runtime.h>
#include <cuda_bf16.h>
#include <math.h>
#include <cstdint>

#define N_PTS   262144
#define DIM     512
#define HID     256
#define NSEG    64
#define LN_EPS  1e-5f

#define MTILE   128     // rows per score CTA (divides SEG_LEN=4096)
#define NTILE   (N_PTS / MTILE)   // 2048
#define KC      64      // K-chunk (64 bf16 = 128 B row = SW128 atom width)
#define NCHUNK  (DIM / KC)

// ---------------- scratch (static device globals; no runtime allocation) ----
__device__ float          g_pnum[(size_t)NTILE * DIM];   // per-tile weighted sums
__device__ float          g_pden[NTILE];                 // per-tile sum of exp
__device__ __nv_bfloat16  g_w1hi[HID * DIM];   // hi(w1*g)
__device__ __nv_bfloat16  g_w1lo[HID * DIM];   // lo(w1*g)
__device__ float          g_c[HID];            // sum_k w1[j,k]*g[k]
__device__ float          g_d[HID];            // sum_k w1[j,k]*beta[k] + b1[j]

// ---------------- helpers ---------------------------------------------------
__device__ __forceinline__ uint32_t smem_u32(const void* p) {
    uint32_t a;
    asm("{ .reg .u64 t; cvta.to.shared.u64 t, %1; cvt.u32.u64 %0, t; }"
        : "=r"(a) : "l"(p));
    return a;
}
#define SWZ128(o) ((o) ^ (((o) >> 3) & 0x70))

#define CP_ASYNC16(dst, src)                                                   \
    asm volatile("cp.async.cg.shared.global [%0], [%1], 16;" :: "r"(dst), "l"(src))
#define CP_COMMIT() asm volatile("cp.async.commit_group;" ::: "memory")
#define CP_WAIT0()  asm volatile("cp.async.wait_group 0;" ::: "memory")
#define FENCE_ASYNC() asm volatile("fence.proxy.async.shared::cta;" ::: "memory")

__device__ __forceinline__ uint32_t pack_bf2(float a, float b) {
    __nv_bfloat162 t = __floats2bfloat162_rn(a, b);
    return *(uint32_t*)&t;
}
__device__ __forceinline__ float gelu_exact(float h) {
    return 0.5f * h * (1.0f + erff(h * 0.70710678118654752f));
}

// ---------------- tcgen05 helpers (only compiled on sm_103a passes) ---------
#if defined(__CUDA_ARCH_FEAT_SM103_ALL) || defined(__CUDA_ARCH_FEAT_SM100_ALL) || defined(__CUDA_ARCH_FEAT_SM101_ALL)
#define HAVE_TCGEN05 1

__device__ __forceinline__ uint32_t elect_one() {
    uint32_t p;
    asm volatile("{\n\t.reg .pred p;\n\t"
                 "elect.sync _|p, 0xFFFFFFFF;\n\t"
                 "selp.b32 %0, 1, 0, p;\n\t}" : "=r"(p));
    return p;
}
static constexpr uint64_t DESC_BASE_SW128 =
    (uint64_t(2) << 61) | (uint64_t(1) << 46) | (uint64_t(64) << 32) | (uint64_t(1) << 16);
#define MAKE_DESC(addr) (DESC_BASE_SW128 | ((uint64_t)((addr) >> 4) & 0x3FFF))

#define MBAR_INIT(a, c) \
    asm volatile("mbarrier.init.shared.b64 [%0], %1;" :: "r"(a), "r"(c) : "memory")
#define MBAR_WAIT(a, ph) do {                                                  \
    uint32_t _m = (a), _p = (ph), _d;                                          \
    asm volatile("{\n\t.reg .pred p;\n\t"                                      \
        "mbarrier.try_wait.parity.acquire.cta.shared::cta.b64 p, [%1], %2;\n\t"\
        "selp.b32 %0, 1, 0, p;\n\t}" : "=r"(_d) : "r"(_m), "r"(_p) : "memory");\
    if (!_d) {                                                                 \
        asm volatile("{\n\t.reg .pred P1;\n\t"                                 \
          "W%=:\n\t"                                                           \
          "mbarrier.try_wait.parity.acquire.cta.shared::cta.b64 P1, [%0], %1, 0x989680;\n\t" \
          "@P1 bra.uni D%=;\n\t"                                               \
          "bra.uni W%=;\n\t"                                                   \
          "D%=:\n\t}" :: "r"(_m), "r"(_p) : "memory");                         \
    } } while (0)

#define TC_ALLOC(sa, n) \
    asm volatile("tcgen05.alloc.cta_group::1.sync.aligned.shared::cta.b32 [%0], %1;" \
                 :: "r"(sa), "r"(n) : "memory")
#define TC_RELINQ() \
    asm volatile("tcgen05.relinquish_alloc_permit.cta_group::1.sync.aligned;")
#define TC_DEALLOC(t, n) \
    asm volatile("tcgen05.dealloc.cta_group::1.sync.aligned.b32 %0, %1;" :: "r"(t), "r"(n))
#define TC_COMMIT(mb) \
    asm volatile("tcgen05.commit.cta_group::1.mbarrier::arrive::one.shared::cluster.b64 [%0];" \
                 :: "r"(mb) : "memory")
#define TC_FENCE_AFTER()  asm volatile("tcgen05.fence::after_thread_sync;"  ::: "memory")
#define TC_FENCE_BEFORE() asm volatile("tcgen05.fence::before_thread_sync;" ::: "memory")
#define TC_WAIT_LD()      asm volatile("tcgen05.wait::ld.sync.aligned;" ::: "memory")

#define TC_LD_X32(r, ta)                                                       \
    asm volatile("tcgen05.ld.sync.aligned.32x32b.x32.b32 "                     \
        "{%0, %1, %2, %3, %4, %5, %6, %7, "                                    \
        " %8, %9, %10, %11, %12, %13, %14, %15, "                              \
        " %16, %17, %18, %19, %20, %21, %22, %23, "                            \
        " %24, %25, %26, %27, %28, %29, %30, %31}, [%32];"                     \
        : "=r"((r)[0]),  "=r"((r)[1]),  "=r"((r)[2]),  "=r"((r)[3]),           \
          "=r"((r)[4]),  "=r"((r)[5]),  "=r"((r)[6]),  "=r"((r)[7]),           \
          "=r"((r)[8]),  "=r"((r)[9]),  "=r"((r)[10]), "=r"((r)[11]),          \
          "=r"((r)[12]), "=r"((r)[13]), "=r"((r)[14]), "=r"((r)[15]),          \
          "=r"((r)[16]), "=r"((r)[17]), "=r"((r)[18]), "=r"((r)[19]),          \
          "=r"((r)[20]), "=r"((r)[21]), "=r"((r)[22]), "=r"((r)[23]),          \
          "=r"((r)[24]), "=r"((r)[25]), "=r"((r)[26]), "=r"((r)[27]),          \
          "=r"((r)[28]), "=r"((r)[29]), "=r"((r)[30]), "=r"((r)[31])           \
        : "r"(ta))

__device__ __forceinline__ void tc_mma_f16_ss(uint32_t d, uint64_t a, uint64_t b,
                                              uint32_t idesc, bool acc) {
    uint32_t en = acc ? 1u : 0u;
    asm volatile("{\n\t.reg .pred p;\n\t"
                 "setp.ne.u32 p, %5, 0;\n\t"
                 "tcgen05.mma.cta_group::1.kind::f16 [%0], %1, %2, %3, {%4, %4, %4, %4}, p;\n\t}"
                 :: "r"(d), "l"(a), "l"(b), "r"(idesc), "r"(0u), "r"(en)
                 : "memory");
}
// idesc: dtype=F32, a=BF16, b=BF16, N=256, M=128
#define TC_IDESC ((1u << 4) | (1u << 7) | (1u << 10) | ((HID / 8) << 17) | ((MTILE / 16) << 24))
#endif  // tcgen05

// ---------------- smem layout (bytes) for score_fused -----------------------
#define SM_MU      0      // 128 f32 (reused as exp(s) after epilogue)
#define SM_RS      512
#define SM_C       1024   // 256 f32: c_j
#define SM_D       2048   // 256 f32: d_j
#define SM_W2      3072   // 256 f32
#define SM_RED     4096   // 512 f32 (epilogue partials) + den partials @ +2048
#define SM_TMEM_OFF 6144  // TMEM base ptr (4B)
#define SM_MBARB   6152   // mbarrier (8B)
#define SM_A       8192   // AHI 16KB @ +0, ALO 16KB @ +16384 ; reused as 32KB pool buf
#define SM_A_LO    16384
#define SM_B       40960  // BHI 32KB @ +0, BLO 32KB @ +32768 ; ends 106496
#define SM_B_LO    32768
#define SM_TOTAL   106496 // x2 CTAs = 212992 <= 228KB carveout

// ---------------------------------------------------------------------------
// Kernel 0: w1 -> w1*g bf16 hi/lo, plus c_j = sum(w1*g), d_j = sum(w1*beta)+b1
// ---------------------------------------------------------------------------
__global__ __launch_bounds__(128) void w1cvt_kernel(
    const float* __restrict__ w1, const float* __restrict__ lng,
    const float* __restrict__ lnb, const float* __restrict__ b1)
{
    __shared__ float redc[4], redd[4];
    int j = blockIdx.x;
    int t = threadIdx.x;
    int c0 = t * 4;
    float csum = 0.f, dsum = 0.f;
#pragma unroll
    for (int k = 0; k < 4; k++) {
        int c = c0 + k;
        float w = w1[(size_t)j * DIM + c];
        float wt = w * lng[c];
        __nv_bfloat16 hi = __float2bfloat16_rn(wt);
        float lo = wt - __bfloat162float(hi);
        g_w1hi[(size_t)j * DIM + c] = hi;
        g_w1lo[(size_t)j * DIM + c] = __float2bfloat16_rn(lo);
        csum += wt;
        dsum += w * lnb[c];
    }
#pragma unroll
    for (int m = 16; m; m >>= 1) {
        csum += __shfl_xor_sync(0xffffffffu, csum, m);
        dsum += __shfl_xor_sync(0xffffffffu, dsum, m);
    }
    if ((t & 31) == 0) { redc[t >> 5] = csum; redd[t >> 5] = dsum; }
    __syncthreads();
    if (t == 0) {
        g_c[j] = redc[0] + redc[1] + redc[2] + redc[3];
        g_d[j] = redd[0] + redd[1] + redd[2] + redd[3] + b1[j];
    }
}

// ---------------------------------------------------------------------------
// Kernel 1: raw-feats bf16-split tcgen05 GEMM + LN-affine + GELU + w2 dot
//           -> unshifted exp -> FUSED partial pooling (num/den per tile).
// 512 threads, 128 rows x 256 hid per CTA, 2 CTAs/SM.
// ---------------------------------------------------------------------------
__global__ __launch_bounds__(512, 2)
void score_fused(const float* __restrict__ feats,
                 const float* __restrict__ w2,
                 const float* __restrict__ b2)
{
    extern __shared__ char smem[];
    uint32_t sb = smem_u32(smem);
    int tid  = threadIdx.x;
    int w    = tid >> 5, lane = tid & 31;
    int row0 = blockIdx.x * MTILE;

    float* s_mu  = (float*)(smem + SM_MU);
    float* s_c   = (float*)(smem + SM_C);
    float* s_d   = (float*)(smem + SM_D);
    float* s_w2  = (float*)(smem + SM_W2);

#ifdef HAVE_TCGEN05
    // =======================================================================
    // tcgen05 path (runs on GB300)
    // =======================================================================
    float* s_rs  = (float*)(smem + SM_RS);
    float* s_red = (float*)(smem + SM_RED);

    if (w == 0) { TC_ALLOC(sb + SM_TMEM_OFF, 256); TC_RELINQ(); }
    if (tid == 0) MBAR_INIT(sb + SM_MBARB, 1);

    // staging roles
    int arow = tid >> 2, aq = tid & 3;        // A: thread = (row, 16-col quarter)
    int brow = tid >> 1, bh = tid & 1;        // B: thread = (hid row, 32-col half)
    const float* aft = feats + (size_t)(row0 + arow) * DIM + aq * 16;

    uint32_t a_sw  = SWZ128((uint32_t)(arow * 128 + aq * 32));
    uint32_t a_sw2 = SWZ128((uint32_t)(arow * 128 + aq * 32 + 16));
    const __nv_bfloat16* bsrc_h = g_w1hi + (size_t)brow * DIM + bh * 32;
    const __nv_bfloat16* bsrc_l = g_w1lo + (size_t)brow * DIM + bh * 32;
    uint32_t b_sw[4];
#pragma unroll
    for (int j = 0; j < 4; j++) b_sw[j] = SWZ128((uint32_t)(brow * 128 + bh * 64 + j * 16));

#define STAGE_B(cc) do {                                                       \
        const __nv_bfloat16* sh_ = bsrc_h + (cc) * KC;                         \
        const __nv_bfloat16* sl_ = bsrc_l + (cc) * KC;                         \
        _Pragma("unroll")                                                      \
        for (int j = 0; j < 4; j++) {                                          \
            CP_ASYNC16(sb + SM_B + b_sw[j],           sh_ + j * 8);            \
            CP_ASYNC16(sb + SM_B + SM_B_LO + b_sw[j], sl_ + j * 8);            \
        }                                                                      \
    } while (0)

    float a_sum = 0.f, a_sq = 0.f;

#define PREP_A(cc, HP, LP) do {                                                \
        const float4* fr = (const float4*)(aft + (cc) * KC);                   \
        _Pragma("unroll")                                                      \
        for (int q_ = 0; q_ < 4; q_++) {                                       \
            float4 f = fr[q_];                                                 \
            a_sum += f.x + f.y + f.z + f.w;                                    \
            a_sq  += f.x * f.x + f.y * f.y + f.z * f.z + f.w * f.w;            \
            __nv_bfloat162 h01 = __floats2bfloat162_rn(f.x, f.y);              \
            __nv_bfloat162 h23 = __floats2bfloat162_rn(f.z, f.w);              \
            (HP)[q_ * 2]     = *(uint32_t*)&h01;                               \
            (HP)[q_ * 2 + 1] = *(uint32_t*)&h23;                               \
            (LP)[q_ * 2]     = pack_bf2(f.x - __bfloat162float(h01.x),         \
                                        f.y - __bfloat162float(h01.y));        \
            (LP)[q_ * 2 + 1] = pack_bf2(f.z - __bfloat162float(h23.x),         \
                                        f.w - __bfloat162float(h23.y));        \
        }                                                                      \
    } while (0)

#define STORE_A(HP, LP) do {                                                   \
        *(uint4*)(smem + SM_A + a_sw)            = *(uint4*)&(HP)[0];          \
        *(uint4*)(smem + SM_A + a_sw2)           = *(uint4*)&(HP)[4];          \
        *(uint4*)(smem + SM_A + SM_A_LO + a_sw)  = *(uint4*)&(LP)[0];          \
        *(uint4*)(smem + SM_A + SM_A_LO + a_sw2) = *(uint4*)&(LP)[4];          \
    } while (0)

    // ---- prologue: stage chunk 0, load params ----
    uint32_t hp[8], lp[8];
    STAGE_B(0);
    CP_COMMIT();
    PREP_A(0, hp, lp);
    STORE_A(hp, lp);
    for (int i = tid; i < HID; i += 512) { s_c[i] = g_c[i]; s_d[i] = g_d[i]; s_w2[i] = w2[i]; }
    CP_WAIT0();
    FENCE_ASYNC();
    __syncthreads();

    uint32_t tmem;
    asm volatile("ld.shared.b32 %0, [%1];" : "=r"(tmem) : "r"(sb + SM_TMEM_OFF));

    for (int c = 0; c < NCHUNK; c++) {
        if (w == 0 && elect_one()) {
            uint64_t adh = MAKE_DESC(sb + SM_A);
            uint64_t adl = MAKE_DESC(sb + SM_A + SM_A_LO);
            uint64_t bdh = MAKE_DESC(sb + SM_B);
            uint64_t bdl = MAKE_DESC(sb + SM_B + SM_B_LO);
#pragma unroll
            for (int s = 0; s < 4; s++)
                tc_mma_f16_ss(tmem, adh + s * 2, bdh + s * 2, TC_IDESC, !(c == 0 && s == 0));
#pragma unroll
            for (int s = 0; s < 4; s++)
                tc_mma_f16_ss(tmem, adh + s * 2, bdl + s * 2, TC_IDESC, true);
#pragma unroll
            for (int s = 0; s < 4; s++)
                tc_mma_f16_ss(tmem, adl + s * 2, bdh + s * 2, TC_IDESC, true);
            TC_COMMIT(sb + SM_MBARB);
        }
        if (c + 1 < NCHUNK) PREP_A(c + 1, hp, lp);
        MBAR_WAIT(sb + SM_MBARB, c & 1);
        if (c + 1 < NCHUNK) {
            STAGE_B(c + 1);
            CP_COMMIT();
            STORE_A(hp, lp);
            CP_WAIT0();
            FENCE_ASYNC();
        }
        __syncthreads();
    }

    // finalize row stats (quad-reduce: lanes aq=0..3 share row)
    a_sum += __shfl_xor_sync(0xffffffffu, a_sum, 1);
    a_sq  += __shfl_xor_sync(0xffffffffu, a_sq,  1);
    a_sum += __shfl_xor_sync(0xffffffffu, a_sum, 2);
    a_sq  += __shfl_xor_sync(0xffffffffu, a_sq,  2);
    if ((lane & 3) == 0) {
        float mu = a_sum * (1.0f / DIM);
        float var = a_sq * (1.0f / DIM) - mu * mu;
        s_mu[arow] = mu;
        s_rs[arow] = rsqrtf(var + LN_EPS);
    }
    TC_FENCE_AFTER();
    __syncthreads();

    // --- GELU epilogue: 16 warps; warp w -> rows (w&3)*32, cols (w>>2)*64 ---
    {
        int rsub = w & 3, q = w >> 2;
        int row = rsub * 32 + lane;
        float rs = s_rs[row];
        float nrsmu = -rs * s_mu[row];
        float acc = 0.f;
#pragma unroll
        for (int half = 0; half < 2; half++) {
            uint32_t r_[32];
            TC_LD_X32(r_, tmem + q * 64 + half * 32);
            TC_WAIT_LD();
#pragma unroll
            for (int j = 0; j < 32; j++) {
                int col = q * 64 + half * 32 + j;
                float h = fmaf(rs, __uint_as_float(r_[j]), fmaf(nrsmu, s_c[col], s_d[col]));
                acc = fmaf(s_w2[col], gelu_exact(h), acc);
            }
        }
        TC_FENCE_BEFORE();
        s_red[q * 128 + row] = acc;
    }
    __syncthreads();
    if (w == 0) TC_DEALLOC(tmem, 256);

    // --- s -> unshifted exp (s_mu region reused as s_e) ---
    if (tid < MTILE) {
        float s = s_red[tid] + s_red[128 + tid] + s_red[256 + tid] + s_red[384 + tid] + b2[0];
        s_mu[tid] = expf(s);   // s_e
    }
    __syncthreads();

#else
    // =======================================================================
    // non-sm_103a fallback: scalar score path (never runs on GB300)
    // =======================================================================
    for (int i = tid; i < HID; i += 512) { s_c[i] = g_c[i]; s_d[i] = g_d[i]; s_w2[i] = w2[i]; }
    __syncthreads();
    if (tid < MTILE) {
        int row = row0 + tid;
        const float* fr = feats + (size_t)row * DIM;
        float sum = 0.f, sq = 0.f;
        for (int k = 0; k < DIM; k++) { float v = fr[k]; sum += v; sq += v * v; }
        float mu = sum * (1.0f / DIM);
        float rs = rsqrtf(sq * (1.0f / DIM) - mu * mu + LN_EPS);
        float acc = 0.f;
        for (int j = 0; j < HID; j++) {
            float dot = 0.f;
            for (int k = 0; k < DIM; k++) {
                float wt = __bfloat162float(g_w1hi[(size_t)j * DIM + k]) +
                           __bfloat162float(g_w1lo[(size_t)j * DIM + k]);
                dot = fmaf(wt, fr[k], dot);
            }
            float h = rs * dot - rs * mu * s_c[j] + s_d[j];
            acc = fmaf(s_w2[j], gelu_exact(h), acc);
        }
        s_mu[tid] = expf(acc + b2[0]);   // s_e
    }
    __syncthreads();
#endif

    // =======================================================================
    // FUSED POOLING (common): partial num[512] + den for this 128-row tile.
    // warp w -> rows w*8 .. w*8+7 ; lane -> dims lane*16 .. lane*16+15
    // =======================================================================
    {
        float* s_e  = s_mu;                     // exp(s) per row
        float* pbuf = (float*)(smem + SM_A);    // 16 x 512 f32 = 32 KB (A tile free)
        float pacc[16];
#pragma unroll
        for (int k = 0; k < 16; k++) pacc[k] = 0.f;
#pragma unroll
        for (int r = 0; r < 8; r++) {
            int row = w * 8 + r;
            float e = s_e[row];
            const float4* fp = (const float4*)(feats + (size_t)(row0 + row) * DIM) + lane * 4;
#pragma unroll
            for (int q = 0; q < 4; q++) {
                float4 f = fp[q];
                pacc[q * 4 + 0] = fmaf(e, f.x, pacc[q * 4 + 0]);
                pacc[q * 4 + 1] = fmaf(e, f.y, pacc[q * 4 + 1]);
                pacc[q * 4 + 2] = fmaf(e, f.z, pacc[q * 4 + 2]);
                pacc[q * 4 + 3] = fmaf(e, f.w, pacc[q * 4 + 3]);
            }
        }
        float4* dst = (float4*)(pbuf + w * DIM + lane * 16);
#pragma unroll
        for (int q = 0; q < 4; q++)
            dst[q] = make_float4(pacc[q * 4], pacc[q * 4 + 1], pacc[q * 4 + 2], pacc[q * 4 + 3]);

        // den partial: rows 0..127 live in lanes of warps 0..3 (tid<128)
        float dpart = (tid < MTILE) ? s_e[tid] : 0.f;
#pragma unroll
        for (int m = 16; m; m >>= 1) dpart += __shfl_xor_sync(0xffffffffu, dpart, m);
        if (w < 4 && lane == 0) ((float*)(smem + SM_RED + 2048))[w] = dpart;
        __syncthreads();

        // reduce 16 warp-partials per dim; write tile outputs
        float sum = 0.f;
#pragma unroll
        for (int wi = 0; wi < 16; wi++) sum += pbuf[wi * DIM + tid];
        g_pnum[(size_t)blockIdx.x * DIM + tid] = sum;
        if (tid == 0) {
            float* dp = (float*)(smem + SM_RED + 2048);
            g_pden[blockIdx.x] = dp[0] + dp[1] + dp[2] + dp[3];
        }
    }
}

// ---------------------------------------------------------------------------
// Kernel 2: reduce 32 tile-partials per scene, divide -> out [64 x 512]
// ---------------------------------------------------------------------------
__global__ __launch_bounds__(512) void pool2_kernel(float* __restrict__ out)
{
    int s = blockIdx.x, d = threadIdx.x;
    float num = 0.f, den = 0.f;
#pragma unroll
    for (int t = 0; t < 32; t++) {
        num += g_pnum[(size_t)(s * 32 + t) * DIM + d];
        den += g_pden[s * 32 + t];
    }
    out[s * DIM + d] = num / den;
}

// ---------------------------------------------------------------------------
extern "C" void kernel_launch(void* const* d_in, const int* in_sizes, int n_in,
                              void* d_out, int out_size)
{
    const float* feats = (const float*)d_in[0];
    const float* lng   = (const float*)d_in[1];
    const float* lnb   = (const float*)d_in[2];
    const float* w1    = (const float*)d_in[3];
    const float* b1    = (const float*)d_in[4];
    const float* w2    = (const float*)d_in[5];
    const float* b2    = (const float*)d_in[6];
    float* out = (float*)d_out;

    static int attr_done = 0;
    if (!attr_done) {
        cudaFuncSetAttribute(score_fused, cudaFuncAttributeMaxDynamicSharedMemorySize, SM_TOTAL);
        attr_done = 1;
    }

    w1cvt_kernel<<<HID, 128>>>(w1, lng, lnb, b1);
    score_fused<<<NTILE, 512, SM_TOTAL>>>(feats, w2, b2);
    pool2_kernel<<<NSEG, 512>>>(out);
}

// round 16
// speedup vs baseline: 1.6395x; 1.6395x over previous
#include <cuda_runtime.h>
#include <cuda_bf16.h>
#include <math.h>
#include <cstdint>

#define N_PTS   262144
#define DIM     512
#define HID     256
#define NSEG    64
#define LN_EPS  1e-5f

#define MTILE   128     // rows per score CTA (divides SEG_LEN=4096)
#define NTILE   (N_PTS / MTILE)   // 2048
#define KC      64      // K-chunk (64 bf16 = 128 B row = SW128 atom width)
#define NCHUNK  (DIM / KC)

// ---------------- scratch (static device globals; no runtime allocation) ----
__device__ float          g_pnum[(size_t)NTILE * DIM];   // per-tile weighted sums
__device__ float          g_pden[NTILE];                 // per-tile sum of exp
__device__ __nv_bfloat16  g_w1hi[HID * DIM];   // hi(w1*g)
__device__ __nv_bfloat16  g_w1lo[HID * DIM];   // lo(w1*g)
__device__ float          g_c[HID];            // sum_k w1[j,k]*g[k]
__device__ float          g_d[HID];            // sum_k w1[j,k]*beta[k] + b1[j]

// ---------------- helpers ---------------------------------------------------
__device__ __forceinline__ uint32_t smem_u32(const void* p) {
    uint32_t a;
    asm("{ .reg .u64 t; cvta.to.shared.u64 t, %1; cvt.u32.u64 %0, t; }"
        : "=r"(a) : "l"(p));
    return a;
}
#define SWZ128(o) ((o) ^ (((o) >> 3) & 0x70))

#define CP_ASYNC16(dst, src)                                                   \
    asm volatile("cp.async.cg.shared.global [%0], [%1], 16;" :: "r"(dst), "l"(src))
#define CP_COMMIT() asm volatile("cp.async.commit_group;" ::: "memory")
#define CP_WAIT0()  asm volatile("cp.async.wait_group 0;" ::: "memory")
#define FENCE_ASYNC() asm volatile("fence.proxy.async.shared::cta;" ::: "memory")

__device__ __forceinline__ uint32_t pack_bf2(float a, float b) {
    __nv_bfloat162 t = __floats2bfloat162_rn(a, b);
    return *(uint32_t*)&t;
}
__device__ __forceinline__ float gelu_exact(float h) {
    return 0.5f * h * (1.0f + erff(h * 0.70710678118654752f));
}

// ---------------- tcgen05 helpers (only compiled on sm_103a passes) ---------
#if defined(__CUDA_ARCH_FEAT_SM103_ALL) || defined(__CUDA_ARCH_FEAT_SM100_ALL) || defined(__CUDA_ARCH_FEAT_SM101_ALL)
#define HAVE_TCGEN05 1

__device__ __forceinline__ uint32_t elect_one() {
    uint32_t p;
    asm volatile("{\n\t.reg .pred p;\n\t"
                 "elect.sync _|p, 0xFFFFFFFF;\n\t"
                 "selp.b32 %0, 1, 0, p;\n\t}" : "=r"(p));
    return p;
}
static constexpr uint64_t DESC_BASE_SW128 =
    (uint64_t(2) << 61) | (uint64_t(1) << 46) | (uint64_t(64) << 32) | (uint64_t(1) << 16);
#define MAKE_DESC(addr) (DESC_BASE_SW128 | ((uint64_t)((addr) >> 4) & 0x3FFF))

#define MBAR_INIT(a, c) \
    asm volatile("mbarrier.init.shared.b64 [%0], %1;" :: "r"(a), "r"(c) : "memory")
#define MBAR_WAIT(a, ph) do {                                                  \
    uint32_t _m = (a), _p = (ph), _d;                                          \
    asm volatile("{\n\t.reg .pred p;\n\t"                                      \
        "mbarrier.try_wait.parity.acquire.cta.shared::cta.b64 p, [%1], %2;\n\t"\
        "selp.b32 %0, 1, 0, p;\n\t}" : "=r"(_d) : "r"(_m), "r"(_p) : "memory");\
    if (!_d) {                                                                 \
        asm volatile("{\n\t.reg .pred P1;\n\t"                                 \
          "W%=:\n\t"                                                           \
          "mbarrier.try_wait.parity.acquire.cta.shared::cta.b64 P1, [%0], %1, 0x989680;\n\t" \
          "@P1 bra.uni D%=;\n\t"                                               \
          "bra.uni W%=;\n\t"                                                   \
          "D%=:\n\t}" :: "r"(_m), "r"(_p) : "memory");                         \
    } } while (0)

#define TC_ALLOC(sa, n) \
    asm volatile("tcgen05.alloc.cta_group::1.sync.aligned.shared::cta.b32 [%0], %1;" \
                 :: "r"(sa), "r"(n) : "memory")
#define TC_RELINQ() \
    asm volatile("tcgen05.relinquish_alloc_permit.cta_group::1.sync.aligned;")
#define TC_DEALLOC(t, n) \
    asm volatile("tcgen05.dealloc.cta_group::1.sync.aligned.b32 %0, %1;" :: "r"(t), "r"(n))
#define TC_COMMIT(mb) \
    asm volatile("tcgen05.commit.cta_group::1.mbarrier::arrive::one.shared::cluster.b64 [%0];" \
                 :: "r"(mb) : "memory")
#define TC_FENCE_AFTER()  asm volatile("tcgen05.fence::after_thread_sync;"  ::: "memory")
#define TC_FENCE_BEFORE() asm volatile("tcgen05.fence::before_thread_sync;" ::: "memory")
#define TC_WAIT_LD()      asm volatile("tcgen05.wait::ld.sync.aligned;" ::: "memory")

#define TC_LD_X32(r, ta)                                                       \
    asm volatile("tcgen05.ld.sync.aligned.32x32b.x32.b32 "                     \
        "{%0, %1, %2, %3, %4, %5, %6, %7, "                                    \
        " %8, %9, %10, %11, %12, %13, %14, %15, "                              \
        " %16, %17, %18, %19, %20, %21, %22, %23, "                            \
        " %24, %25, %26, %27, %28, %29, %30, %31}, [%32];"                     \
        : "=r"((r)[0]),  "=r"((r)[1]),  "=r"((r)[2]),  "=r"((r)[3]),           \
          "=r"((r)[4]),  "=r"((r)[5]),  "=r"((r)[6]),  "=r"((r)[7]),           \
          "=r"((r)[8]),  "=r"((r)[9]),  "=r"((r)[10]), "=r"((r)[11]),          \
          "=r"((r)[12]), "=r"((r)[13]), "=r"((r)[14]), "=r"((r)[15]),          \
          "=r"((r)[16]), "=r"((r)[17]), "=r"((r)[18]), "=r"((r)[19]),          \
          "=r"((r)[20]), "=r"((r)[21]), "=r"((r)[22]), "=r"((r)[23]),          \
          "=r"((r)[24]), "=r"((r)[25]), "=r"((r)[26]), "=r"((r)[27]),          \
          "=r"((r)[28]), "=r"((r)[29]), "=r"((r)[30]), "=r"((r)[31])           \
        : "r"(ta))

__device__ __forceinline__ void tc_mma_f16_ss(uint32_t d, uint64_t a, uint64_t b,
                                              uint32_t idesc, bool acc) {
    uint32_t en = acc ? 1u : 0u;
    asm volatile("{\n\t.reg .pred p;\n\t"
                 "setp.ne.u32 p, %5, 0;\n\t"
                 "tcgen05.mma.cta_group::1.kind::f16 [%0], %1, %2, %3, {%4, %4, %4, %4}, p;\n\t}"
                 :: "r"(d), "l"(a), "l"(b), "r"(idesc), "r"(0u), "r"(en)
                 : "memory");
}
// idesc: dtype=F32, a=BF16, b=BF16, N=256, M=128
#define TC_IDESC ((1u << 4) | (1u << 7) | (1u << 10) | ((HID / 8) << 17) | ((MTILE / 16) << 24))
#endif  // tcgen05

// ---------------- smem layout (bytes) for score_fused -----------------------
#define SM_MU      0      // 128 f32 (reused as exp(s) after epilogue)
#define SM_RS      512
#define SM_C       1024   // 256 f32: c_j
#define SM_D       2048   // 256 f32: d_j
#define SM_W2      3072   // 256 f32
#define SM_RED     4096   // 512 f32 (epilogue partials) + den partials @ +2048
#define SM_TMEM_OFF 6144  // TMEM base ptr (4B)
#define SM_MBARB   6152   // mbarrier (8B)
#define SM_A       8192   // AHI 16KB @ +0, ALO 16KB @ +16384
#define SM_A_LO    16384
#define SM_B       40960  // BHI 32KB @ +0, BLO 32KB @ +32768 ; ends 106496
#define SM_B_LO    32768
#define SM_TOTAL   106496 // x2 CTAs = 212992 <= 228KB carveout

// ---------------------------------------------------------------------------
// Kernel 0: w1 -> w1*g bf16 hi/lo, plus c_j = sum(w1*g), d_j = sum(w1*beta)+b1
// ---------------------------------------------------------------------------
__global__ __launch_bounds__(128) void w1cvt_kernel(
    const float* __restrict__ w1, const float* __restrict__ lng,
    const float* __restrict__ lnb, const float* __restrict__ b1)
{
    __shared__ float redc[4], redd[4];
    int j = blockIdx.x;
    int t = threadIdx.x;
    int c0 = t * 4;
    float csum = 0.f, dsum = 0.f;
#pragma unroll
    for (int k = 0; k < 4; k++) {
        int c = c0 + k;
        float w = w1[(size_t)j * DIM + c];
        float wt = w * lng[c];
        __nv_bfloat16 hi = __float2bfloat16_rn(wt);
        float lo = wt - __bfloat162float(hi);
        g_w1hi[(size_t)j * DIM + c] = hi;
        g_w1lo[(size_t)j * DIM + c] = __float2bfloat16_rn(lo);
        csum += wt;
        dsum += w * lnb[c];
    }
#pragma unroll
    for (int m = 16; m; m >>= 1) {
        csum += __shfl_xor_sync(0xffffffffu, csum, m);
        dsum += __shfl_xor_sync(0xffffffffu, dsum, m);
    }
    if ((t & 31) == 0) { redc[t >> 5] = csum; redd[t >> 5] = dsum; }
    __syncthreads();
    if (t == 0) {
        g_c[j] = redc[0] + redc[1] + redc[2] + redc[3];
        g_d[j] = redd[0] + redd[1] + redd[2] + redd[3] + b1[j];
    }
}

// ---------------------------------------------------------------------------
// Kernel 1: raw-feats bf16-split tcgen05 GEMM + LN-affine + GELU + w2 dot
//           -> unshifted exp -> spill-free fused pooling (num/den per tile).
// 512 threads, 128 rows x 256 hid per CTA, 2 CTAs/SM.
// ---------------------------------------------------------------------------
__global__ __launch_bounds__(512, 2)
void score_fused(const float* __restrict__ feats,
                 const float* __restrict__ w2,
                 const float* __restrict__ b2)
{
    extern __shared__ char smem[];
    uint32_t sb = smem_u32(smem);
    int tid  = threadIdx.x;
    int w    = tid >> 5, lane = tid & 31;
    int row0 = blockIdx.x * MTILE;

    float* s_mu  = (float*)(smem + SM_MU);
    float* s_c   = (float*)(smem + SM_C);
    float* s_d   = (float*)(smem + SM_D);
    float* s_w2  = (float*)(smem + SM_W2);

#ifdef HAVE_TCGEN05
    // =======================================================================
    // tcgen05 path (runs on GB300)
    // =======================================================================
    float* s_rs  = (float*)(smem + SM_RS);
    float* s_red = (float*)(smem + SM_RED);

    if (w == 0) { TC_ALLOC(sb + SM_TMEM_OFF, 256); TC_RELINQ(); }
    if (tid == 0) MBAR_INIT(sb + SM_MBARB, 1);

    // staging roles
    int arow = tid >> 2, aq = tid & 3;        // A: thread = (row, 16-col quarter)
    int brow = tid >> 1, bh = tid & 1;        // B: thread = (hid row, 32-col half)
    const float* aft = feats + (size_t)(row0 + arow) * DIM + aq * 16;

    uint32_t a_sw  = SWZ128((uint32_t)(arow * 128 + aq * 32));
    uint32_t a_sw2 = SWZ128((uint32_t)(arow * 128 + aq * 32 + 16));
    const __nv_bfloat16* bsrc_h = g_w1hi + (size_t)brow * DIM + bh * 32;
    const __nv_bfloat16* bsrc_l = g_w1lo + (size_t)brow * DIM + bh * 32;
    uint32_t b_sw[4];
#pragma unroll
    for (int j = 0; j < 4; j++) b_sw[j] = SWZ128((uint32_t)(brow * 128 + bh * 64 + j * 16));

#define STAGE_B(cc) do {                                                       \
        const __nv_bfloat16* sh_ = bsrc_h + (cc) * KC;                         \
        const __nv_bfloat16* sl_ = bsrc_l + (cc) * KC;                         \
        _Pragma("unroll")                                                      \
        for (int j = 0; j < 4; j++) {                                          \
            CP_ASYNC16(sb + SM_B + b_sw[j],           sh_ + j * 8);            \
            CP_ASYNC16(sb + SM_B + SM_B_LO + b_sw[j], sl_ + j * 8);            \
        }                                                                      \
    } while (0)

    float a_sum = 0.f, a_sq = 0.f;

#define PREP_A(cc, HP, LP) do {                                                \
        const float4* fr = (const float4*)(aft + (cc) * KC);                   \
        _Pragma("unroll")                                                      \
        for (int q_ = 0; q_ < 4; q_++) {                                       \
            float4 f = fr[q_];                                                 \
            a_sum += f.x + f.y + f.z + f.w;                                    \
            a_sq  += f.x * f.x + f.y * f.y + f.z * f.z + f.w * f.w;            \
            __nv_bfloat162 h01 = __floats2bfloat162_rn(f.x, f.y);              \
            __nv_bfloat162 h23 = __floats2bfloat162_rn(f.z, f.w);              \
            (HP)[q_ * 2]     = *(uint32_t*)&h01;                               \
            (HP)[q_ * 2 + 1] = *(uint32_t*)&h23;                               \
            (LP)[q_ * 2]     = pack_bf2(f.x - __bfloat162float(h01.x),         \
                                        f.y - __bfloat162float(h01.y));        \
            (LP)[q_ * 2 + 1] = pack_bf2(f.z - __bfloat162float(h23.x),         \
                                        f.w - __bfloat162float(h23.y));        \
        }                                                                      \
    } while (0)

#define STORE_A(HP, LP) do {                                                   \
        *(uint4*)(smem + SM_A + a_sw)            = *(uint4*)&(HP)[0];          \
        *(uint4*)(smem + SM_A + a_sw2)           = *(uint4*)&(HP)[4];          \
        *(uint4*)(smem + SM_A + SM_A_LO + a_sw)  = *(uint4*)&(LP)[0];          \
        *(uint4*)(smem + SM_A + SM_A_LO + a_sw2) = *(uint4*)&(LP)[4];          \
    } while (0)

    // ---- prologue: stage chunk 0, load params ----
    uint32_t hp[8], lp[8];
    STAGE_B(0);
    CP_COMMIT();
    PREP_A(0, hp, lp);
    STORE_A(hp, lp);
    for (int i = tid; i < HID; i += 512) { s_c[i] = g_c[i]; s_d[i] = g_d[i]; s_w2[i] = w2[i]; }
    CP_WAIT0();
    FENCE_ASYNC();
    __syncthreads();

    uint32_t tmem;
    asm volatile("ld.shared.b32 %0, [%1];" : "=r"(tmem) : "r"(sb + SM_TMEM_OFF));

    for (int c = 0; c < NCHUNK; c++) {
        if (w == 0 && elect_one()) {
            uint64_t adh = MAKE_DESC(sb + SM_A);
            uint64_t adl = MAKE_DESC(sb + SM_A + SM_A_LO);
            uint64_t bdh = MAKE_DESC(sb + SM_B);
            uint64_t bdl = MAKE_DESC(sb + SM_B + SM_B_LO);
#pragma unroll
            for (int s = 0; s < 4; s++)
                tc_mma_f16_ss(tmem, adh + s * 2, bdh + s * 2, TC_IDESC, !(c == 0 && s == 0));
#pragma unroll
            for (int s = 0; s < 4; s++)
                tc_mma_f16_ss(tmem, adh + s * 2, bdl + s * 2, TC_IDESC, true);
#pragma unroll
            for (int s = 0; s < 4; s++)
                tc_mma_f16_ss(tmem, adl + s * 2, bdh + s * 2, TC_IDESC, true);
            TC_COMMIT(sb + SM_MBARB);
        }
        if (c + 1 < NCHUNK) PREP_A(c + 1, hp, lp);
        MBAR_WAIT(sb + SM_MBARB, c & 1);
        if (c + 1 < NCHUNK) {
            STAGE_B(c + 1);
            CP_COMMIT();
            STORE_A(hp, lp);
            CP_WAIT0();
            FENCE_ASYNC();
        }
        __syncthreads();
    }

    // finalize row stats (quad-reduce: lanes aq=0..3 share row)
    a_sum += __shfl_xor_sync(0xffffffffu, a_sum, 1);
    a_sq  += __shfl_xor_sync(0xffffffffu, a_sq,  1);
    a_sum += __shfl_xor_sync(0xffffffffu, a_sum, 2);
    a_sq  += __shfl_xor_sync(0xffffffffu, a_sq,  2);
    if ((lane & 3) == 0) {
        float mu = a_sum * (1.0f / DIM);
        float var = a_sq * (1.0f / DIM) - mu * mu;
        s_mu[arow] = mu;
        s_rs[arow] = rsqrtf(var + LN_EPS);
    }
    TC_FENCE_AFTER();
    __syncthreads();

    // --- GELU epilogue: 16 warps; warp w -> rows (w&3)*32, cols (w>>2)*64 ---
    {
        int rsub = w & 3, q = w >> 2;
        int row = rsub * 32 + lane;
        float rs = s_rs[row];
        float nrsmu = -rs * s_mu[row];
        float acc = 0.f;
#pragma unroll
        for (int half = 0; half < 2; half++) {
            uint32_t r_[32];
            TC_LD_X32(r_, tmem + q * 64 + half * 32);
            TC_WAIT_LD();
#pragma unroll
            for (int j = 0; j < 32; j++) {
                int col = q * 64 + half * 32 + j;
                float h = fmaf(rs, __uint_as_float(r_[j]), fmaf(nrsmu, s_c[col], s_d[col]));
                acc = fmaf(s_w2[col], gelu_exact(h), acc);
            }
        }
        TC_FENCE_BEFORE();
        s_red[q * 128 + row] = acc;
    }
    __syncthreads();
    if (w == 0) TC_DEALLOC(tmem, 256);

    // --- s -> unshifted exp (s_mu region reused as s_e) ---
    if (tid < MTILE) {
        float s = s_red[tid] + s_red[128 + tid] + s_red[256 + tid] + s_red[384 + tid] + b2[0];
        s_mu[tid] = expf(s);   // s_e
    }
    __syncthreads();

#else
    // =======================================================================
    // non-sm_103a fallback: scalar score path (never runs on GB300)
    // =======================================================================
    for (int i = tid; i < HID; i += 512) { s_c[i] = g_c[i]; s_d[i] = g_d[i]; s_w2[i] = w2[i]; }
    __syncthreads();
    if (tid < MTILE) {
        int row = row0 + tid;
        const float* fr = feats + (size_t)row * DIM;
        float sum = 0.f, sq = 0.f;
        for (int k = 0; k < DIM; k++) { float v = fr[k]; sum += v; sq += v * v; }
        float mu = sum * (1.0f / DIM);
        float rs = rsqrtf(sq * (1.0f / DIM) - mu * mu + LN_EPS);
        float acc = 0.f;
        for (int j = 0; j < HID; j++) {
            float dot = 0.f;
            for (int k = 0; k < DIM; k++) {
                float wt = __bfloat162float(g_w1hi[(size_t)j * DIM + k]) +
                           __bfloat162float(g_w1lo[(size_t)j * DIM + k]);
                dot = fmaf(wt, fr[k], dot);
            }
            float h = rs * dot - rs * mu * s_c[j] + s_d[j];
            acc = fmaf(s_w2[j], gelu_exact(h), acc);
        }
        s_mu[tid] = expf(acc + b2[0]);   // s_e
    }
    __syncthreads();
#endif

    // =======================================================================
    // FUSED POOLING (spill-free): thread owns dim d = tid; loop 128 rows.
    // Warp reads 128 contiguous bytes per row (perfect coalescing);
    // s_e[r] is an smem broadcast. Single accumulator register.
    // =======================================================================
    {
        float* s_e = s_mu;
        const float* fb = feats + (size_t)row0 * DIM + tid;
        float acc = 0.f;
#pragma unroll 4
        for (int r = 0; r < MTILE; r++)
            acc = fmaf(s_e[r], fb[(size_t)r * DIM], acc);
        g_pnum[(size_t)blockIdx.x * DIM + tid] = acc;

        // den partial: rows 0..127 live in lanes of warps 0..3 (tid<128)
        float dpart = (tid < MTILE) ? s_e[tid] : 0.f;
#pragma unroll
        for (int m = 16; m; m >>= 1) dpart += __shfl_xor_sync(0xffffffffu, dpart, m);
        float* dp = (float*)(smem + SM_RED + 2048);
        if (w < 4 && lane == 0) dp[w] = dpart;
        __syncthreads();
        if (tid == 0) g_pden[blockIdx.x] = dp[0] + dp[1] + dp[2] + dp[3];
    }
}

// ---------------------------------------------------------------------------
// Kernel 2: reduce 32 tile-partials per scene, divide -> out [64 x 512]
// ---------------------------------------------------------------------------
__global__ __launch_bounds__(512) void pool2_kernel(float* __restrict__ out)
{
    int s = blockIdx.x, d = threadIdx.x;
    float num = 0.f, den = 0.f;
#pragma unroll
    for (int t = 0; t < 32; t++) {
        num += g_pnum[(size_t)(s * 32 + t) * DIM + d];
        den += g_pden[s * 32 + t];
    }
    out[s * DIM + d] = num / den;
}

// ---------------------------------------------------------------------------
extern "C" void kernel_launch(void* const* d_in, const int* in_sizes, int n_in,
                              void* d_out, int out_size)
{
    const float* feats = (const float*)d_in[0];
    const float* lng   = (const float*)d_in[1];
    const float* lnb   = (const float*)d_in[2];
    const float* w1    = (const float*)d_in[3];
    const float* b1    = (const float*)d_in[4];
    const float* w2    = (const float*)d_in[5];
    const float* b2    = (const float*)d_in[6];
    float* out = (float*)d_out;

    static int attr_done = 0;
    if (!attr_done) {
        cudaFuncSetAttribute(score_fused, cudaFuncAttributeMaxDynamicSharedMemorySize, SM_TOTAL);
        attr_done = 1;
    }

    w1cvt_kernel<<<HID, 128>>>(w1, lng, lnb, b1);
    score_fused<<<NTILE, 512, SM_TOTAL>>>(feats, w2, b2);
    pool2_kernel<<<NSEG, 512>>>(out);
}

// round 17
// speedup vs baseline: 1.7881x; 1.0906x over previous
#include <cuda_runtime.h>
#include <cuda_bf16.h>
#include <math.h>
#include <cstdint>

#define N_PTS   262144
#define DIM     512
#define HID     256
#define NSEG    64
#define LN_EPS  1e-5f

#define MTILE   128     // rows per score CTA (divides SEG_LEN=4096)
#define NTILE   (N_PTS / MTILE)   // 2048
#define KC      64      // K-chunk (64 bf16 = 128 B row = SW128 atom width)
#define NCHUNK  (DIM / KC)

// ---------------- scratch (static device globals; no runtime allocation) ----
__device__ float          g_pnum[(size_t)NTILE * DIM];   // per-tile weighted sums
__device__ float          g_pden[NTILE];                 // per-tile sum of exp
__device__ __nv_bfloat16  g_w1hi[HID * DIM];   // hi(w1*g)
__device__ __nv_bfloat16  g_w1lo[HID * DIM];   // lo(w1*g)
__device__ float          g_c[HID];            // sum_k w1[j,k]*g[k]
__device__ float          g_d[HID];            // sum_k w1[j,k]*beta[k] + b1[j]

// ---------------- helpers ---------------------------------------------------
__device__ __forceinline__ uint32_t smem_u32(const void* p) {
    uint32_t a;
    asm("{ .reg .u64 t; cvta.to.shared.u64 t, %1; cvt.u32.u64 %0, t; }"
        : "=r"(a) : "l"(p));
    return a;
}
#define SWZ128(o) ((o) ^ (((o) >> 3) & 0x70))

#define CP_ASYNC16(dst, src)                                                   \
    asm volatile("cp.async.cg.shared.global [%0], [%1], 16;" :: "r"(dst), "l"(src))
#define CP_COMMIT() asm volatile("cp.async.commit_group;" ::: "memory")
#define CP_WAIT0()  asm volatile("cp.async.wait_group 0;" ::: "memory")
#define FENCE_ASYNC() asm volatile("fence.proxy.async.shared::cta;" ::: "memory")

__device__ __forceinline__ uint32_t pack_bf2(float a, float b) {
    __nv_bfloat162 t = __floats2bfloat162_rn(a, b);
    return *(uint32_t*)&t;
}
__device__ __forceinline__ float gelu_exact(float h) {
    return 0.5f * h * (1.0f + erff(h * 0.70710678118654752f));
}

// ---------------- tcgen05 helpers (only compiled on sm_103a passes) ---------
#if defined(__CUDA_ARCH_FEAT_SM103_ALL) || defined(__CUDA_ARCH_FEAT_SM100_ALL) || defined(__CUDA_ARCH_FEAT_SM101_ALL)
#define HAVE_TCGEN05 1

__device__ __forceinline__ uint32_t elect_one() {
    uint32_t p;
    asm volatile("{\n\t.reg .pred p;\n\t"
                 "elect.sync _|p, 0xFFFFFFFF;\n\t"
                 "selp.b32 %0, 1, 0, p;\n\t}" : "=r"(p));
    return p;
}
static constexpr uint64_t DESC_BASE_SW128 =
    (uint64_t(2) << 61) | (uint64_t(1) << 46) | (uint64_t(64) << 32) | (uint64_t(1) << 16);
#define MAKE_DESC(addr) (DESC_BASE_SW128 | ((uint64_t)((addr) >> 4) & 0x3FFF))

#define MBAR_INIT(a, c) \
    asm volatile("mbarrier.init.shared.b64 [%0], %1;" :: "r"(a), "r"(c) : "memory")
#define MBAR_WAIT(a, ph) do {                                                  \
    uint32_t _m = (a), _p = (ph), _d;                                          \
    asm volatile("{\n\t.reg .pred p;\n\t"                                      \
        "mbarrier.try_wait.parity.acquire.cta.shared::cta.b64 p, [%1], %2;\n\t"\
        "selp.b32 %0, 1, 0, p;\n\t}" : "=r"(_d) : "r"(_m), "r"(_p) : "memory");\
    if (!_d) {                                                                 \
        asm volatile("{\n\t.reg .pred P1;\n\t"                                 \
          "W%=:\n\t"                                                           \
          "mbarrier.try_wait.parity.acquire.cta.shared::cta.b64 P1, [%0], %1, 0x989680;\n\t" \
          "@P1 bra.uni D%=;\n\t"                                               \
          "bra.uni W%=;\n\t"                                                   \
          "D%=:\n\t}" :: "r"(_m), "r"(_p) : "memory");                         \
    } } while (0)

#define TC_ALLOC(sa, n) \
    asm volatile("tcgen05.alloc.cta_group::1.sync.aligned.shared::cta.b32 [%0], %1;" \
                 :: "r"(sa), "r"(n) : "memory")
#define TC_RELINQ() \
    asm volatile("tcgen05.relinquish_alloc_permit.cta_group::1.sync.aligned;")
#define TC_DEALLOC(t, n) \
    asm volatile("tcgen05.dealloc.cta_group::1.sync.aligned.b32 %0, %1;" :: "r"(t), "r"(n))
#define TC_COMMIT(mb) \
    asm volatile("tcgen05.commit.cta_group::1.mbarrier::arrive::one.shared::cluster.b64 [%0];" \
                 :: "r"(mb) : "memory")
#define TC_FENCE_AFTER()  asm volatile("tcgen05.fence::after_thread_sync;"  ::: "memory")
#define TC_FENCE_BEFORE() asm volatile("tcgen05.fence::before_thread_sync;" ::: "memory")
#define TC_WAIT_LD()      asm volatile("tcgen05.wait::ld.sync.aligned;" ::: "memory")

#define TC_LD_X32(r, ta)                                                       \
    asm volatile("tcgen05.ld.sync.aligned.32x32b.x32.b32 "                     \
        "{%0, %1, %2, %3, %4, %5, %6, %7, "                                    \
        " %8, %9, %10, %11, %12, %13, %14, %15, "                              \
        " %16, %17, %18, %19, %20, %21, %22, %23, "                            \
        " %24, %25, %26, %27, %28, %29, %30, %31}, [%32];"                     \
        : "=r"((r)[0]),  "=r"((r)[1]),  "=r"((r)[2]),  "=r"((r)[3]),           \
          "=r"((r)[4]),  "=r"((r)[5]),  "=r"((r)[6]),  "=r"((r)[7]),           \
          "=r"((r)[8]),  "=r"((r)[9]),  "=r"((r)[10]), "=r"((r)[11]),          \
          "=r"((r)[12]), "=r"((r)[13]), "=r"((r)[14]), "=r"((r)[15]),          \
          "=r"((r)[16]), "=r"((r)[17]), "=r"((r)[18]), "=r"((r)[19]),          \
          "=r"((r)[20]), "=r"((r)[21]), "=r"((r)[22]), "=r"((r)[23]),          \
          "=r"((r)[24]), "=r"((r)[25]), "=r"((r)[26]), "=r"((r)[27]),          \
          "=r"((r)[28]), "=r"((r)[29]), "=r"((r)[30]), "=r"((r)[31])           \
        : "r"(ta))

__device__ __forceinline__ void tc_mma_f16_ss(uint32_t d, uint64_t a, uint64_t b,
                                              uint32_t idesc, bool acc) {
    uint32_t en = acc ? 1u : 0u;
    asm volatile("{\n\t.reg .pred p;\n\t"
                 "setp.ne.u32 p, %5, 0;\n\t"
                 "tcgen05.mma.cta_group::1.kind::f16 [%0], %1, %2, %3, {%4, %4, %4, %4}, p;\n\t}"
                 :: "r"(d), "l"(a), "l"(b), "r"(idesc), "r"(0u), "r"(en)
                 : "memory");
}
// idesc: dtype=F32, a=BF16, b=BF16, N=256, M=128
#define TC_IDESC ((1u << 4) | (1u << 7) | (1u << 10) | ((HID / 8) << 17) | ((MTILE / 16) << 24))
#endif  // tcgen05

// ---------------- smem layout (bytes) for score_fused -----------------------
#define SM_MU      0      // 128 f32 (reused as exp(s) after epilogue)
#define SM_RS      512
#define SM_C       1024   // 256 f32: c_j
#define SM_D       2048   // 256 f32: d_j
#define SM_W2      3072   // 256 f32
#define SM_RED     4096   // 512 f32 (epilogue partials) + den partials @ +2048
#define SM_TMEM_OFF 6144  // TMEM base ptr (4B)
#define SM_MBARB   6152   // mbarrier (8B)
#define SM_A       8192   // AHI 16KB @ +0, ALO 16KB @ +16384
#define SM_A_LO    16384
#define SM_B       40960  // BHI 32KB @ +0, BLO 32KB @ +32768 ; ends 106496
#define SM_B_LO    32768
#define SM_TOTAL   106496 // x2 CTAs = 212992 <= 228KB carveout

// ---------------------------------------------------------------------------
// Kernel 0: w1 -> w1*g bf16 hi/lo, plus c_j = sum(w1*g), d_j = sum(w1*beta)+b1
// ---------------------------------------------------------------------------
__global__ __launch_bounds__(128) void w1cvt_kernel(
    const float* __restrict__ w1, const float* __restrict__ lng,
    const float* __restrict__ lnb, const float* __restrict__ b1)
{
    __shared__ float redc[4], redd[4];
    int j = blockIdx.x;
    int t = threadIdx.x;
    int c0 = t * 4;
    float csum = 0.f, dsum = 0.f;
#pragma unroll
    for (int k = 0; k < 4; k++) {
        int c = c0 + k;
        float w = w1[(size_t)j * DIM + c];
        float wt = w * lng[c];
        __nv_bfloat16 hi = __float2bfloat16_rn(wt);
        float lo = wt - __bfloat162float(hi);
        g_w1hi[(size_t)j * DIM + c] = hi;
        g_w1lo[(size_t)j * DIM + c] = __float2bfloat16_rn(lo);
        csum += wt;
        dsum += w * lnb[c];
    }
#pragma unroll
    for (int m = 16; m; m >>= 1) {
        csum += __shfl_xor_sync(0xffffffffu, csum, m);
        dsum += __shfl_xor_sync(0xffffffffu, dsum, m);
    }
    if ((t & 31) == 0) { redc[t >> 5] = csum; redd[t >> 5] = dsum; }
    __syncthreads();
    if (t == 0) {
        g_c[j] = redc[0] + redc[1] + redc[2] + redc[3];
        g_d[j] = redd[0] + redd[1] + redd[2] + redd[3] + b1[j];
    }
}

// ---------------------------------------------------------------------------
// Kernel 1: raw-feats bf16-split tcgen05 GEMM + LN-affine + GELU + w2 dot
//           -> unshifted exp -> spill-free fused pooling (num/den per tile).
// 512 threads, 128 rows x 256 hid per CTA, 2 CTAs/SM.
// ---------------------------------------------------------------------------
__global__ __launch_bounds__(512, 2)
void score_fused(const float* __restrict__ feats,
                 const float* __restrict__ w2,
                 const float* __restrict__ b2)
{
    extern __shared__ char smem[];
    uint32_t sb = smem_u32(smem);
    int tid  = threadIdx.x;
    int w    = tid >> 5, lane = tid & 31;
    int row0 = blockIdx.x * MTILE;

    float* s_mu  = (float*)(smem + SM_MU);
    float* s_c   = (float*)(smem + SM_C);
    float* s_d   = (float*)(smem + SM_D);
    float* s_w2  = (float*)(smem + SM_W2);

#ifdef HAVE_TCGEN05
    // =======================================================================
    // tcgen05 path (runs on GB300)
    // =======================================================================
    float* s_rs  = (float*)(smem + SM_RS);
    float* s_red = (float*)(smem + SM_RED);

    if (w == 0) { TC_ALLOC(sb + SM_TMEM_OFF, 256); TC_RELINQ(); }
    if (tid == 0) MBAR_INIT(sb + SM_MBARB, 1);

    // staging roles
    int arow = tid >> 2, aq = tid & 3;        // A: thread = (row, 16-col quarter)
    int brow = tid >> 1, bh = tid & 1;        // B: thread = (hid row, 32-col half)
    const float* aft = feats + (size_t)(row0 + arow) * DIM + aq * 16;

    uint32_t a_sw  = SWZ128((uint32_t)(arow * 128 + aq * 32));
    uint32_t a_sw2 = SWZ128((uint32_t)(arow * 128 + aq * 32 + 16));
    const __nv_bfloat16* bsrc_h = g_w1hi + (size_t)brow * DIM + bh * 32;
    const __nv_bfloat16* bsrc_l = g_w1lo + (size_t)brow * DIM + bh * 32;
    uint32_t b_sw[4];
#pragma unroll
    for (int j = 0; j < 4; j++) b_sw[j] = SWZ128((uint32_t)(brow * 128 + bh * 64 + j * 16));

#define STAGE_B(cc) do {                                                       \
        const __nv_bfloat16* sh_ = bsrc_h + (cc) * KC;                         \
        const __nv_bfloat16* sl_ = bsrc_l + (cc) * KC;                         \
        _Pragma("unroll")                                                      \
        for (int j = 0; j < 4; j++) {                                          \
            CP_ASYNC16(sb + SM_B + b_sw[j],           sh_ + j * 8);            \
            CP_ASYNC16(sb + SM_B + SM_B_LO + b_sw[j], sl_ + j * 8);            \
        }                                                                      \
    } while (0)

    float a_sum = 0.f, a_sq = 0.f;

#define PREP_A(cc, HP, LP) do {                                                \
        const float4* fr = (const float4*)(aft + (cc) * KC);                   \
        _Pragma("unroll")                                                      \
        for (int q_ = 0; q_ < 4; q_++) {                                       \
            float4 f = fr[q_];                                                 \
            a_sum += f.x + f.y + f.z + f.w;                                    \
            a_sq  += f.x * f.x + f.y * f.y + f.z * f.z + f.w * f.w;            \
            __nv_bfloat162 h01 = __floats2bfloat162_rn(f.x, f.y);              \
            __nv_bfloat162 h23 = __floats2bfloat162_rn(f.z, f.w);              \
            (HP)[q_ * 2]     = *(uint32_t*)&h01;                               \
            (HP)[q_ * 2 + 1] = *(uint32_t*)&h23;                               \
            (LP)[q_ * 2]     = pack_bf2(f.x - __bfloat162float(h01.x),         \
                                        f.y - __bfloat162float(h01.y));        \
            (LP)[q_ * 2 + 1] = pack_bf2(f.z - __bfloat162float(h23.x),         \
                                        f.w - __bfloat162float(h23.y));        \
        }                                                                      \
    } while (0)

#define STORE_A(HP, LP) do {                                                   \
        *(uint4*)(smem + SM_A + a_sw)            = *(uint4*)&(HP)[0];          \
        *(uint4*)(smem + SM_A + a_sw2)           = *(uint4*)&(HP)[4];          \
        *(uint4*)(smem + SM_A + SM_A_LO + a_sw)  = *(uint4*)&(LP)[0];          \
        *(uint4*)(smem + SM_A + SM_A_LO + a_sw2) = *(uint4*)&(LP)[4];          \
    } while (0)

    // ---- prologue: stage chunk 0, load params ----
    uint32_t hp[8], lp[8];
    STAGE_B(0);
    CP_COMMIT();
    PREP_A(0, hp, lp);
    STORE_A(hp, lp);
    for (int i = tid; i < HID; i += 512) { s_c[i] = g_c[i]; s_d[i] = g_d[i]; s_w2[i] = w2[i]; }
    CP_WAIT0();
    FENCE_ASYNC();
    __syncthreads();

    uint32_t tmem;
    asm volatile("ld.shared.b32 %0, [%1];" : "=r"(tmem) : "r"(sb + SM_TMEM_OFF));

    for (int c = 0; c < NCHUNK; c++) {
        if (w == 0 && elect_one()) {
            uint64_t adh = MAKE_DESC(sb + SM_A);
            uint64_t adl = MAKE_DESC(sb + SM_A + SM_A_LO);
            uint64_t bdh = MAKE_DESC(sb + SM_B);
            uint64_t bdl = MAKE_DESC(sb + SM_B + SM_B_LO);
#pragma unroll
            for (int s = 0; s < 4; s++)
                tc_mma_f16_ss(tmem, adh + s * 2, bdh + s * 2, TC_IDESC, !(c == 0 && s == 0));
#pragma unroll
            for (int s = 0; s < 4; s++)
                tc_mma_f16_ss(tmem, adh + s * 2, bdl + s * 2, TC_IDESC, true);
#pragma unroll
            for (int s = 0; s < 4; s++)
                tc_mma_f16_ss(tmem, adl + s * 2, bdh + s * 2, TC_IDESC, true);
            TC_COMMIT(sb + SM_MBARB);
        }
        if (c + 1 < NCHUNK) PREP_A(c + 1, hp, lp);
        MBAR_WAIT(sb + SM_MBARB, c & 1);
        if (c + 1 < NCHUNK) {
            STAGE_B(c + 1);
            CP_COMMIT();
            STORE_A(hp, lp);
            CP_WAIT0();
            FENCE_ASYNC();
        }
        __syncthreads();
    }

    // finalize row stats (quad-reduce: lanes aq=0..3 share row)
    a_sum += __shfl_xor_sync(0xffffffffu, a_sum, 1);
    a_sq  += __shfl_xor_sync(0xffffffffu, a_sq,  1);
    a_sum += __shfl_xor_sync(0xffffffffu, a_sum, 2);
    a_sq  += __shfl_xor_sync(0xffffffffu, a_sq,  2);
    if ((lane & 3) == 0) {
        float mu = a_sum * (1.0f / DIM);
        float var = a_sq * (1.0f / DIM) - mu * mu;
        s_mu[arow] = mu;
        s_rs[arow] = rsqrtf(var + LN_EPS);
    }
    TC_FENCE_AFTER();
    __syncthreads();

    // --- GELU epilogue: 16 warps; warp w -> rows (w&3)*32, cols (w>>2)*64 ---
    {
        int rsub = w & 3, q = w >> 2;
        int row = rsub * 32 + lane;
        float rs = s_rs[row];
        float nrsmu = -rs * s_mu[row];
        float acc = 0.f;
#pragma unroll
        for (int half = 0; half < 2; half++) {
            uint32_t r_[32];
            TC_LD_X32(r_, tmem + q * 64 + half * 32);
            TC_WAIT_LD();
#pragma unroll
            for (int j = 0; j < 32; j++) {
                int col = q * 64 + half * 32 + j;
                float h = fmaf(rs, __uint_as_float(r_[j]), fmaf(nrsmu, s_c[col], s_d[col]));
                acc = fmaf(s_w2[col], gelu_exact(h), acc);
            }
        }
        TC_FENCE_BEFORE();
        s_red[q * 128 + row] = acc;
    }
    __syncthreads();
    if (w == 0) TC_DEALLOC(tmem, 256);

    // --- s -> unshifted exp (s_mu region reused as s_e) ---
    if (tid < MTILE) {
        float s = s_red[tid] + s_red[128 + tid] + s_red[256 + tid] + s_red[384 + tid] + b2[0];
        s_mu[tid] = expf(s);   // s_e
    }
    __syncthreads();

#else
    // =======================================================================
    // non-sm_103a fallback: scalar score path (never runs on GB300)
    // =======================================================================
    for (int i = tid; i < HID; i += 512) { s_c[i] = g_c[i]; s_d[i] = g_d[i]; s_w2[i] = w2[i]; }
    __syncthreads();
    if (tid < MTILE) {
        int row = row0 + tid;
        const float* fr = feats + (size_t)row * DIM;
        float sum = 0.f, sq = 0.f;
        for (int k = 0; k < DIM; k++) { float v = fr[k]; sum += v; sq += v * v; }
        float mu = sum * (1.0f / DIM);
        float rs = rsqrtf(sq * (1.0f / DIM) - mu * mu + LN_EPS);
        float acc = 0.f;
        for (int j = 0; j < HID; j++) {
            float dot = 0.f;
            for (int k = 0; k < DIM; k++) {
                float wt = __bfloat162float(g_w1hi[(size_t)j * DIM + k]) +
                           __bfloat162float(g_w1lo[(size_t)j * DIM + k]);
                dot = fmaf(wt, fr[k], dot);
            }
            float h = rs * dot - rs * mu * s_c[j] + s_d[j];
            acc = fmaf(s_w2[j], gelu_exact(h), acc);
        }
        s_mu[tid] = expf(acc + b2[0]);   // s_e
    }
    __syncthreads();
#endif

    // =======================================================================
    // FUSED POOLING: thread owns dim d = tid. 4 independent accumulators over
    // row quarters (r, r+32, r+64, r+96) break the FMA chain; full unroll
    // front-batches the 128 independent LDGs for high MLP.
    // =======================================================================
    {
        float* s_e = s_mu;
        const float* fb = feats + (size_t)row0 * DIM + tid;
        float p0 = 0.f, p1 = 0.f, p2 = 0.f, p3 = 0.f;
#pragma unroll
        for (int r = 0; r < 32; r++) {
            p0 = fmaf(s_e[r],      fb[(size_t)r * DIM],          p0);
            p1 = fmaf(s_e[r + 32], fb[(size_t)(r + 32) * DIM],   p1);
            p2 = fmaf(s_e[r + 64], fb[(size_t)(r + 64) * DIM],   p2);
            p3 = fmaf(s_e[r + 96], fb[(size_t)(r + 96) * DIM],   p3);
        }
        g_pnum[(size_t)blockIdx.x * DIM + tid] = (p0 + p1) + (p2 + p3);

        // den partial: rows 0..127 live in lanes of warps 0..3 (tid<128)
        float dpart = (tid < MTILE) ? s_e[tid] : 0.f;
#pragma unroll
        for (int m = 16; m; m >>= 1) dpart += __shfl_xor_sync(0xffffffffu, dpart, m);
        float* dp = (float*)(smem + SM_RED + 2048);
        if (w < 4 && lane == 0) dp[w] = dpart;
        __syncthreads();
        if (tid == 0) g_pden[blockIdx.x] = dp[0] + dp[1] + dp[2] + dp[3];
    }
}

// ---------------------------------------------------------------------------
// Kernel 2: reduce 32 tile-partials per scene, divide -> out [64 x 512]
// ---------------------------------------------------------------------------
__global__ __launch_bounds__(512) void pool2_kernel(float* __restrict__ out)
{
    int s = blockIdx.x, d = threadIdx.x;
    float num = 0.f, den = 0.f;
#pragma unroll
    for (int t = 0; t < 32; t++) {
        num += g_pnum[(size_t)(s * 32 + t) * DIM + d];
        den += g_pden[s * 32 + t];
    }
    out[s * DIM + d] = num / den;
}

// ---------------------------------------------------------------------------
extern "C" void kernel_launch(void* const* d_in, const int* in_sizes, int n_in,
                              void* d_out, int out_size)
{
    const float* feats = (const float*)d_in[0];
    const float* lng   = (const float*)d_in[1];
    const float* lnb   = (const float*)d_in[2];
    const float* w1    = (const float*)d_in[3];
    const float* b1    = (const float*)d_in[4];
    const float* w2    = (const float*)d_in[5];
    const float* b2    = (const float*)d_in[6];
    float* out = (float*)d_out;

    static int attr_done = 0;
    if (!attr_done) {
        cudaFuncSetAttribute(score_fused, cudaFuncAttributeMaxDynamicSharedMemorySize, SM_TOTAL);
        attr_done = 1;
    }

    w1cvt_kernel<<<HID, 128>>>(w1, lng, lnb, b1);
    score_fused<<<NTILE, 512, SM_TOTAL>>>(feats, w2, b2);
    pool2_kernel<<<NSEG, 512>>>(out);
}